// round 9
// baseline (speedup 1.0000x reference)
#include <cuda_runtime.h>
#include <cstdint>
#include <math.h>

#define DINL __device__ __forceinline__

constexpr int S_  = 2048;
constexpr int H_  = 2048;
constexpr int NH_ = 16;
constexpr int HD_ = 128;
constexpr int B_  = 2;
constexpr int M_  = B_ * S_;   // 4096

// ---- fp32 scratch (static; no allocations) ----
__device__ __align__(16) float gf_h  [M_ * H_];              // rmsnorm out [m][k]
__device__ __align__(16) float gf_q  [B_ * NH_ * S_ * HD_];  // [bh][s][d]
__device__ __align__(16) float gf_k  [B_ * NH_ * S_ * HD_];
__device__ __align__(16) float gf_v  [B_ * NH_ * S_ * HD_];
__device__ __align__(16) float gf_ctx[M_ * H_];              // [b*s][h*128+d]
__device__ int g_flags[8];   // 0=w 1=x 2=qkv 3=rope 4=attn 5=out 6=x-not-f32

DINL float san(float v, int stage) {
    if (!isfinite(v)) { g_flags[stage] = 1; return 0.f; }
    return v;
}

__global__ void zero_flags_kernel() {
    if (threadIdx.x < 8) g_flags[threadIdx.x] = 0;
}

// ---- probe: is x plausible as fp32 N(0, 0.5)? ----
__global__ void probe_kernel(const float* __restrict__ x) {
    __shared__ int bad;
    if (threadIdx.x == 0) bad = 0;
    __syncthreads();
    int c = 0;
    for (int i = threadIdx.x; i < 1024; i += 256) {
        float v = x[i];
        bool ok = isfinite(v) && (v == 0.f || (fabsf(v) > 1e-12f && fabsf(v) < 1e4f));
        if (!ok) c++;
    }
    atomicAdd(&bad, c);
    __syncthreads();
    if (threadIdx.x == 0 && bad > 100) g_flags[6] = 1;
}

// ---- RMSNorm: x[4096,2048] f32 -> gf_h ----
__global__ void __launch_bounds__(256) rmsnorm_kernel(const float* __restrict__ x,
                                                      const float* __restrict__ w) {
    int row = blockIdx.x;
    const float* xr = x + (size_t)row * H_;
    float v[8];
    float ss = 0.f;
#pragma unroll
    for (int i = 0; i < 8; i++) {
        v[i] = san(xr[threadIdx.x + i * 256], 1);
        ss += v[i] * v[i];
    }
#pragma unroll
    for (int o = 16; o; o >>= 1) ss += __shfl_xor_sync(0xffffffffu, ss, o);
    __shared__ float red[8];
    if ((threadIdx.x & 31) == 0) red[threadIdx.x >> 5] = ss;
    __syncthreads();
    float tot = 0.f;
#pragma unroll
    for (int i = 0; i < 8; i++) tot += red[i];
    float inv = rsqrtf(tot * (1.f / (float)H_) + 1e-6f);
#pragma unroll
    for (int i = 0; i < 8; i++) {
        int c = threadIdx.x + i * 256;
        gf_h[(size_t)row * H_ + c] = san(v[i] * inv * san(w[c], 1), 1);
    }
}

// ---- SGEMM: C[M,N] = A[M,K] * W[N,K]^T, 128x128x16 tiles, 8x8/thread ----
template<int WHICH>
__global__ void __launch_bounds__(256) gemm_kernel(const float* __restrict__ W,
                                                   float* __restrict__ outp) {
    const float* A = (WHICH == 3) ? gf_ctx : gf_h;

    __shared__ float sA[16][132];   // [k][m], row = 528B (16B-aligned)
    __shared__ float sW[16][132];   // [k][n]

    const int t  = threadIdx.x;
    const int tx = t & 15;          // n-dir
    const int ty = t >> 4;          // m-dir
    const int bm = blockIdx.y, bn = blockIdx.x;

    float acc[8][8];
#pragma unroll
    for (int i = 0; i < 8; i++)
#pragma unroll
        for (int j = 0; j < 8; j++) acc[i][j] = 0.f;

    for (int k0 = 0; k0 < H_; k0 += 16) {
#pragma unroll
        for (int l = 0; l < 2; l++) {
            int li  = t * 2 + l;              // 0..511
            int row = li >> 2;                // 0..127
            int kq  = (li & 3) << 2;          // 0,4,8,12
            float4 a4 = *reinterpret_cast<const float4*>(
                A + (size_t)(bm * 128 + row) * H_ + k0 + kq);
            sA[kq + 0][row] = a4.x; sA[kq + 1][row] = a4.y;
            sA[kq + 2][row] = a4.z; sA[kq + 3][row] = a4.w;
            float4 w4 = *reinterpret_cast<const float4*>(
                W + (size_t)(bn * 128 + row) * H_ + k0 + kq);
            sW[kq + 0][row] = san(w4.x, 0); sW[kq + 1][row] = san(w4.y, 0);
            sW[kq + 2][row] = san(w4.z, 0); sW[kq + 3][row] = san(w4.w, 0);
        }
        __syncthreads();

#pragma unroll
        for (int kk = 0; kk < 16; kk++) {
            float av[8], wv[8];
            *reinterpret_cast<float4*>(av)     = *reinterpret_cast<float4*>(&sA[kk][ty * 8]);
            *reinterpret_cast<float4*>(av + 4) = *reinterpret_cast<float4*>(&sA[kk][ty * 8 + 4]);
            *reinterpret_cast<float4*>(wv)     = *reinterpret_cast<float4*>(&sW[kk][tx * 8]);
            *reinterpret_cast<float4*>(wv + 4) = *reinterpret_cast<float4*>(&sW[kk][tx * 8 + 4]);
#pragma unroll
            for (int i = 0; i < 8; i++)
#pragma unroll
                for (int j = 0; j < 8; j++)
                    acc[i][j] += av[i] * wv[j];
        }
        __syncthreads();
    }

#pragma unroll
    for (int i = 0; i < 8; i++) {
        int m = bm * 128 + ty * 8 + i;
        int b = m >> 11, s = m & 2047;
#pragma unroll
        for (int j = 0; j < 8; j++) {
            int n = bn * 128 + tx * 8 + j;
            if (WHICH < 3) {
                float* dst = (WHICH == 0) ? gf_q : (WHICH == 1) ? gf_k : gf_v;
                int hh = n >> 7, dd = n & 127;
                size_t idx = ((size_t)((b << 4) + hh) << 18) + ((size_t)s << 7) + dd;
                dst[idx] = san(acc[i][j], 2);
            } else {
                outp[(size_t)m * H_ + n] = san(acc[i][j], 5);
            }
        }
    }
}

// ---- RoPE (f32, in place); q gets 1/sqrt(128)*log2(e) folded in ----
__global__ void __launch_bounds__(128) rope_kernel(const int* __restrict__ pos_ids) {
    int row = blockIdx.x * 2 + (threadIdx.x >> 6);   // bh*S + s
    int j   = threadIdx.x & 63;
    int s   = row & (S_ - 1);
    int bh  = row >> 11;
    int b   = bh >> 4;
    int p   = pos_ids[(b << 11) + s] & (S_ - 1);

    float inv_freq = expf((float)j * (-9.210340371976184f / 64.f));
    float ang = (float)p * inv_freq;
    float sn, cs;
    sincosf(ang, &sn, &cs);

    size_t base = (size_t)row * HD_ + j;
    const float QS = 0.088388347648318447f * 1.4426950408889634f;

    float q0 = san(gf_q[base], 3), q1 = san(gf_q[base + 64], 3);
    gf_q[base]      = (q0 * cs - q1 * sn) * QS;
    gf_q[base + 64] = (q1 * cs + q0 * sn) * QS;

    float k0 = san(gf_k[base], 3), k1 = san(gf_k[base + 64], 3);
    gf_k[base]      = k0 * cs - k1 * sn;
    gf_k[base + 64] = k1 * cs + k0 * sn;
}

// ---- Flash attention (f32, causal): 32 q rows/CTA, 32-key tiles ----
__global__ void __launch_bounds__(256) fa_kernel() {
    const int qt = (int)gridDim.x - 1 - (int)blockIdx.x;   // long tiles first
    const int bh = blockIdx.y;
    const int b  = bh >> 4, h = bh & 15;
    const int t  = threadIdx.x;

    __shared__ float sQ [32][132];
    __shared__ float sKV[32][132];
    __shared__ float sS [32][33];
    __shared__ float sM[32], sL[32], sAl[32];

    const float* qb = gf_q + ((size_t)bh * S_ + (size_t)qt * 32) * HD_;
    const float* kb0 = gf_k + (size_t)bh * S_ * HD_;
    const float* vb0 = gf_v + (size_t)bh * S_ * HD_;

#pragma unroll
    for (int i = 0; i < 16; i++) {
        int idx = t + i * 256;
        sQ[idx >> 7][idx & 127] = qb[idx];
    }
    if (t < 32) { sM[t] = -1e30f; sL[t] = 0.f; }

    const int r  = t >> 3;         // q row 0..31
    const int dc = t & 7;          // d chunk (16 floats)
    const int dbase = dc * 16;
    float o[16];
#pragma unroll
    for (int i = 0; i < 16; i++) o[i] = 0.f;
    __syncthreads();

    const int nkt = qt + 1;
    const int qrow_g = qt * 32 + r;
    for (int kt = 0; kt < nkt; kt++) {
        // K tile
        const float* kb = kb0 + (size_t)kt * 32 * HD_;
#pragma unroll
        for (int i = 0; i < 16; i++) {
            int idx = t + i * 256;
            sKV[idx >> 7][idx & 127] = kb[idx];
        }
        __syncthreads();

        // scores: this thread does rows r, keys j0..j0+3
        {
            const int j0 = dc * 4;
            float s0 = 0.f, s1 = 0.f, s2 = 0.f, s3 = 0.f;
            for (int k = 0; k < 128; k += 4) {
                float4 q4 = *reinterpret_cast<float4*>(&sQ[r][k]);
                float4 k40 = *reinterpret_cast<float4*>(&sKV[j0 + 0][k]);
                float4 k41 = *reinterpret_cast<float4*>(&sKV[j0 + 1][k]);
                float4 k42 = *reinterpret_cast<float4*>(&sKV[j0 + 2][k]);
                float4 k43 = *reinterpret_cast<float4*>(&sKV[j0 + 3][k]);
                s0 += q4.x * k40.x + q4.y * k40.y + q4.z * k40.z + q4.w * k40.w;
                s1 += q4.x * k41.x + q4.y * k41.y + q4.z * k41.z + q4.w * k41.w;
                s2 += q4.x * k42.x + q4.y * k42.y + q4.z * k42.z + q4.w * k42.w;
                s3 += q4.x * k43.x + q4.y * k43.y + q4.z * k43.z + q4.w * k43.w;
            }
            int kg = kt * 32 + j0;
            sS[r][j0 + 0] = (kg + 0 > qrow_g) ? -1e30f : s0;
            sS[r][j0 + 1] = (kg + 1 > qrow_g) ? -1e30f : s1;
            sS[r][j0 + 2] = (kg + 2 > qrow_g) ? -1e30f : s2;
            sS[r][j0 + 3] = (kg + 3 > qrow_g) ? -1e30f : s3;
        }
        __syncthreads();

        // online softmax per row (threads 0..31), base-2 domain
        if (t < 32) {
            float mx = -1e30f;
#pragma unroll
            for (int j = 0; j < 32; j++) mx = fmaxf(mx, sS[t][j]);
            float mn = fmaxf(sM[t], mx);
            float al = exp2f(fminf(sM[t] - mn, 0.f));
            float ls = 0.f;
#pragma unroll
            for (int j = 0; j < 32; j++) {
                float p = exp2f(fminf(sS[t][j] - mn, 0.f));
                sS[t][j] = p;
                ls += p;
            }
            sL[t] = sL[t] * al + ls;
            sM[t] = mn;
            sAl[t] = al;
        }
        __syncthreads();

        float al = sAl[r];
#pragma unroll
        for (int i = 0; i < 16; i++) o[i] *= al;

        // V tile (reuse sKV)
        const float* vb = vb0 + (size_t)kt * 32 * HD_;
#pragma unroll
        for (int i = 0; i < 16; i++) {
            int idx = t + i * 256;
            sKV[idx >> 7][idx & 127] = vb[idx];
        }
        __syncthreads();

        // O += P * V
#pragma unroll 4
        for (int j = 0; j < 32; j++) {
            float p = sS[r][j];
            float4 v0 = *reinterpret_cast<float4*>(&sKV[j][dbase]);
            float4 v1 = *reinterpret_cast<float4*>(&sKV[j][dbase + 4]);
            float4 v2 = *reinterpret_cast<float4*>(&sKV[j][dbase + 8]);
            float4 v3 = *reinterpret_cast<float4*>(&sKV[j][dbase + 12]);
            o[0]  += p * v0.x; o[1]  += p * v0.y; o[2]  += p * v0.z; o[3]  += p * v0.w;
            o[4]  += p * v1.x; o[5]  += p * v1.y; o[6]  += p * v1.z; o[7]  += p * v1.w;
            o[8]  += p * v2.x; o[9]  += p * v2.y; o[10] += p * v2.z; o[11] += p * v2.w;
            o[12] += p * v3.x; o[13] += p * v3.y; o[14] += p * v3.z; o[15] += p * v3.w;
        }
        __syncthreads();
    }

    float inv = 1.f / fmaxf(sL[r], 1e-20f);
    size_t obase = (size_t)(b * S_ + qt * 32 + r) * H_ + h * 128 + dbase;
#pragma unroll
    for (int i = 0; i < 16; i++) gf_ctx[obase + i] = san(o[i] * inv, 4);
}

// ---- canary: exponent-coded first failing stage into out[0] ----
__global__ void canary_kernel(float* __restrict__ outp) {
    if (threadIdx.x == 0 && blockIdx.x == 0) {
        if (g_flags[6]) { outp[0] += 3.0e38f; return; }   // x not plausible as f32
        const float code[6] = {1e6f, 1e12f, 1e18f, 1e24f, 1e30f, 1e36f};
        for (int i = 0; i < 6; i++) {
            if (g_flags[i]) { outp[0] += code[i]; return; }
        }
    }
}

extern "C" void kernel_launch(void* const* d_in, const int* in_sizes, int n_in,
                              void* d_out, int out_size) {
    // Unit-agnostic input identification: weights = size appearing exactly 4x;
    // x = 2x weight size; of the remaining two, smaller = norm_w, larger = pos.
    int iw[4], nw = 0;
    long long ws = -1;
    for (int i = 0; i < n_in; i++) {
        int cnt = 0;
        for (int j = 0; j < n_in; j++) if (in_sizes[j] == in_sizes[i]) cnt++;
        if (cnt == 4) ws = in_sizes[i];
    }
    int ix = 0, inw = 1, ipos = 6;
    if (ws > 0) {
        int rem[8], nrem = 0;
        for (int i = 0; i < n_in; i++) {
            if (in_sizes[i] == (int)ws && nw < 4) iw[nw++] = i;
            else if ((long long)in_sizes[i] == 2 * ws) ix = i;
            else if (nrem < 8) rem[nrem++] = i;
        }
        if (nrem >= 2) {
            if (in_sizes[rem[0]] <= in_sizes[rem[1]]) { inw = rem[0]; ipos = rem[1]; }
            else                                      { inw = rem[1]; ipos = rem[0]; }
        }
    }
    if (nw < 4) { iw[0] = 2; iw[1] = 3; iw[2] = 4; iw[3] = 5; ix = 0; inw = 1; ipos = 6; }

    const float* x      = (const float*)d_in[ix];
    const float* norm_w = (const float*)d_in[inw];
    const int*   pos    = (const int*)d_in[ipos];
    float* outp = (float*)d_out;

    zero_flags_kernel<<<1, 32>>>();
    probe_kernel<<<1, 256>>>(x);

    rmsnorm_kernel<<<M_, 256>>>(x, norm_w);

    dim3 gg(H_ / 128, M_ / 128);
    gemm_kernel<0><<<gg, 256>>>((const float*)d_in[iw[0]], nullptr);
    gemm_kernel<1><<<gg, 256>>>((const float*)d_in[iw[1]], nullptr);
    gemm_kernel<2><<<gg, 256>>>((const float*)d_in[iw[2]], nullptr);

    rope_kernel<<<(B_ * NH_ * S_) / 2, 128>>>(pos);

    dim3 fg(S_ / 32, B_ * NH_);
    fa_kernel<<<fg, 256>>>();

    gemm_kernel<3><<<gg, 256>>>((const float*)d_in[iw[3]], outp);
    canary_kernel<<<1, 32>>>(outp);
}

// round 11
// speedup vs baseline: 1.2217x; 1.2217x over previous
#include <cuda_runtime.h>
#include <cstdint>
#include <math.h>

#define DINL __device__ __forceinline__

constexpr int S_  = 2048;
constexpr int H_  = 2048;
constexpr int NH_ = 16;
constexpr int HD_ = 128;
constexpr int B_  = 2;
constexpr int M_  = B_ * S_;   // 4096

// ---- fp32 scratch (static; no allocations) ----
__device__ __align__(16) float gf_h  [M_ * H_];              // rmsnorm out [m][k]
__device__ __align__(16) float gf_q  [B_ * NH_ * S_ * HD_];  // [bh][s][d]
__device__ __align__(16) float gf_k  [B_ * NH_ * S_ * HD_];
__device__ __align__(16) float gf_v  [B_ * NH_ * S_ * HD_];
__device__ __align__(16) float gf_ctx[M_ * H_];              // [b*s][h*128+d]
__device__ int g_flags[8];   // 0=w 1=x 2=qkv 3=rope 4=attn 5=out 6=x-not-f32

DINL float san(float v, int stage) {
    if (!isfinite(v)) { g_flags[stage] = 1; return 0.f; }
    return v;
}

__global__ void zero_flags_kernel() {
    if (threadIdx.x < 8) g_flags[threadIdx.x] = 0;
}

// ---- probe: is x plausible as fp32 N(0, 0.5)? ----
__global__ void probe_kernel(const float* __restrict__ x) {
    __shared__ int bad;
    if (threadIdx.x == 0) bad = 0;
    __syncthreads();
    int c = 0;
    for (int i = threadIdx.x; i < 1024; i += 256) {
        float v = x[i];
        bool ok = isfinite(v) && (v == 0.f || (fabsf(v) > 1e-12f && fabsf(v) < 1e4f));
        if (!ok) c++;
    }
    atomicAdd(&bad, c);
    __syncthreads();
    if (threadIdx.x == 0 && bad > 100) g_flags[6] = 1;
}

// ---- RMSNorm: x[4096,2048] f32 -> gf_h ----
__global__ void __launch_bounds__(256) rmsnorm_kernel(const float* __restrict__ x,
                                                      const float* __restrict__ w) {
    int row = blockIdx.x;
    const float* xr = x + (size_t)row * H_;
    float v[8];
    float ss = 0.f;
#pragma unroll
    for (int i = 0; i < 8; i++) {
        v[i] = san(xr[threadIdx.x + i * 256], 1);
        ss += v[i] * v[i];
    }
#pragma unroll
    for (int o = 16; o; o >>= 1) ss += __shfl_xor_sync(0xffffffffu, ss, o);
    __shared__ float red[8];
    if ((threadIdx.x & 31) == 0) red[threadIdx.x >> 5] = ss;
    __syncthreads();
    float tot = 0.f;
#pragma unroll
    for (int i = 0; i < 8; i++) tot += red[i];
    float inv = rsqrtf(tot * (1.f / (float)H_) + 1e-6f);
#pragma unroll
    for (int i = 0; i < 8; i++) {
        int c = threadIdx.x + i * 256;
        gf_h[(size_t)row * H_ + c] = san(v[i] * inv * san(w[c], 1), 1);
    }
}

// ---- tf32 helpers ----
DINL uint32_t f2tf32(float x) {
    uint32_t u;
    asm("cvt.rna.tf32.f32 %0, %1;" : "=r"(u) : "f"(x));
    return u;
}
DINL void mma_tf32(float* c, const uint32_t* a, uint32_t b0, uint32_t b1) {
    asm volatile(
        "mma.sync.aligned.m16n8k8.row.col.f32.tf32.tf32.f32 "
        "{%0,%1,%2,%3}, {%4,%5,%6,%7}, {%8,%9}, {%0,%1,%2,%3};"
        : "+f"(c[0]), "+f"(c[1]), "+f"(c[2]), "+f"(c[3])
        : "r"(a[0]), "r"(a[1]), "r"(a[2]), "r"(a[3]), "r"(b0), "r"(b1));
}

// ---- GEMM (tf32 tensor core): C[M,N] = A[M,K] * W[N,K]^T ----
// 128x128 tile, 8 warps, each warp 64x32 (4x4 frags of m16n8k8).
template<int WHICH>
__global__ void __launch_bounds__(256) gemm_kernel(const float* __restrict__ W,
                                                   float* __restrict__ outp) {
    const float* A = (WHICH == 3) ? gf_ctx : gf_h;

    __shared__ uint32_t sA[16][132];   // [k][m] tf32 bits, pad 132
    __shared__ uint32_t sW[16][132];   // [k][n]

    const int t    = threadIdx.x;
    const int wid  = t >> 5, lane = t & 31;
    const int g    = lane >> 2, tg = lane & 3;     // groupID / thread-in-group
    const int bm   = blockIdx.y, bn = blockIdx.x;
    const int wm   = (wid & 1) * 64, wn = (wid >> 1) * 32;

    float acc[4][4][4];
#pragma unroll
    for (int i = 0; i < 4; i++)
#pragma unroll
        for (int j = 0; j < 4; j++)
#pragma unroll
            for (int c = 0; c < 4; c++) acc[i][j][c] = 0.f;

    for (int k0 = 0; k0 < H_; k0 += 16) {
        // global -> smem (float4), converting to tf32 bits
#pragma unroll
        for (int l = 0; l < 2; l++) {
            int li  = t * 2 + l;              // 0..511
            int row = li >> 2;                // 0..127
            int kq  = (li & 3) << 2;          // 0,4,8,12
            float4 a4 = *reinterpret_cast<const float4*>(
                A + (size_t)(bm * 128 + row) * H_ + k0 + kq);
            sA[kq + 0][row] = f2tf32(a4.x); sA[kq + 1][row] = f2tf32(a4.y);
            sA[kq + 2][row] = f2tf32(a4.z); sA[kq + 3][row] = f2tf32(a4.w);
            float4 w4 = *reinterpret_cast<const float4*>(
                W + (size_t)(bn * 128 + row) * H_ + k0 + kq);
            sW[kq + 0][row] = f2tf32(san(w4.x, 0)); sW[kq + 1][row] = f2tf32(san(w4.y, 0));
            sW[kq + 2][row] = f2tf32(san(w4.z, 0)); sW[kq + 3][row] = f2tf32(san(w4.w, 0));
        }
        __syncthreads();

#pragma unroll
        for (int ks = 0; ks < 2; ks++) {
            const int kb = ks * 8;
            uint32_t af[4][4];
#pragma unroll
            for (int mf = 0; mf < 4; mf++) {
                int r0 = wm + mf * 16 + g;
                af[mf][0] = sA[kb + tg][r0];
                af[mf][1] = sA[kb + tg][r0 + 8];
                af[mf][2] = sA[kb + tg + 4][r0];
                af[mf][3] = sA[kb + tg + 4][r0 + 8];
            }
            uint32_t bfr[4][2];
#pragma unroll
            for (int nf = 0; nf < 4; nf++) {
                int cn = wn + nf * 8 + g;
                bfr[nf][0] = sW[kb + tg][cn];
                bfr[nf][1] = sW[kb + tg + 4][cn];
            }
#pragma unroll
            for (int mf = 0; mf < 4; mf++)
#pragma unroll
                for (int nf = 0; nf < 4; nf++)
                    mma_tf32(acc[mf][nf], af[mf], bfr[nf][0], bfr[nf][1]);
        }
        __syncthreads();
    }

    const int stage = (WHICH < 3) ? 2 : 5;
#pragma unroll
    for (int mf = 0; mf < 4; mf++) {
        int r0 = bm * 128 + wm + mf * 16 + g;
        int r1 = r0 + 8;
        int b0i = r0 >> 11, s0 = r0 & 2047;
        int b1i = r1 >> 11, s1 = r1 & 2047;
#pragma unroll
        for (int nf = 0; nf < 4; nf++) {
            int o = bn * 128 + wn + nf * 8 + 2 * tg;
            float v0 = san(acc[mf][nf][0], stage), v1 = san(acc[mf][nf][1], stage);
            float v2 = san(acc[mf][nf][2], stage), v3 = san(acc[mf][nf][3], stage);
            if (WHICH < 3) {
                float* dst = (WHICH == 0) ? gf_q : (WHICH == 1) ? gf_k : gf_v;
                int hh = o >> 7, dd = o & 127;
                size_t i0 = ((size_t)((b0i << 4) + hh) << 18) + ((size_t)s0 << 7) + dd;
                size_t i1 = ((size_t)((b1i << 4) + hh) << 18) + ((size_t)s1 << 7) + dd;
                dst[i0] = v0; dst[i0 + 1] = v1;
                dst[i1] = v2; dst[i1 + 1] = v3;
            } else {
                outp[(size_t)r0 * H_ + o] = v0; outp[(size_t)r0 * H_ + o + 1] = v1;
                outp[(size_t)r1 * H_ + o] = v2; outp[(size_t)r1 * H_ + o + 1] = v3;
            }
        }
    }
}

// ---- RoPE (f32, in place); q gets 1/sqrt(128)*log2(e) folded in ----
__global__ void __launch_bounds__(128) rope_kernel(const int* __restrict__ pos_ids) {
    int row = blockIdx.x * 2 + (threadIdx.x >> 6);   // bh*S + s
    int j   = threadIdx.x & 63;
    int s   = row & (S_ - 1);
    int bh  = row >> 11;
    int b   = bh >> 4;
    int p   = pos_ids[(b << 11) + s] & (S_ - 1);

    float inv_freq = expf((float)j * (-9.210340371976184f / 64.f));
    float ang = (float)p * inv_freq;
    float sn, cs;
    sincosf(ang, &sn, &cs);

    size_t base = (size_t)row * HD_ + j;
    const float QS = 0.088388347648318447f * 1.4426950408889634f;

    float q0 = san(gf_q[base], 3), q1 = san(gf_q[base + 64], 3);
    gf_q[base]      = (q0 * cs - q1 * sn) * QS;
    gf_q[base + 64] = (q1 * cs + q0 * sn) * QS;

    float k0 = san(gf_k[base], 3), k1 = san(gf_k[base + 64], 3);
    gf_k[base]      = k0 * cs - k1 * sn;
    gf_k[base + 64] = k1 * cs + k0 * sn;
}

// ---- Flash attention (f32, causal): 32 q rows/CTA, 32-key tiles ----
__global__ void __launch_bounds__(256) fa_kernel() {
    const int qt = (int)gridDim.x - 1 - (int)blockIdx.x;   // long tiles first
    const int bh = blockIdx.y;
    const int b  = bh >> 4, h = bh & 15;
    const int t  = threadIdx.x;

    __shared__ float sQ [32][132];
    __shared__ float sKV[32][132];
    __shared__ float sS [32][33];
    __shared__ float sM[32], sL[32], sAl[32];

    const float* qb = gf_q + ((size_t)bh * S_ + (size_t)qt * 32) * HD_;
    const float* kb0 = gf_k + (size_t)bh * S_ * HD_;
    const float* vb0 = gf_v + (size_t)bh * S_ * HD_;

#pragma unroll
    for (int i = 0; i < 16; i++) {
        int idx = t + i * 256;
        sQ[idx >> 7][idx & 127] = qb[idx];
    }
    if (t < 32) { sM[t] = -1e30f; sL[t] = 0.f; }

    const int r  = t >> 3;
    const int dc = t & 7;
    const int dbase = dc * 16;
    float o[16];
#pragma unroll
    for (int i = 0; i < 16; i++) o[i] = 0.f;
    __syncthreads();

    const int nkt = qt + 1;
    const int qrow_g = qt * 32 + r;
    for (int kt = 0; kt < nkt; kt++) {
        const float* kb = kb0 + (size_t)kt * 32 * HD_;
#pragma unroll
        for (int i = 0; i < 16; i++) {
            int idx = t + i * 256;
            sKV[idx >> 7][idx & 127] = kb[idx];
        }
        __syncthreads();

        {
            const int j0 = dc * 4;
            float s0 = 0.f, s1 = 0.f, s2 = 0.f, s3 = 0.f;
            for (int k = 0; k < 128; k += 4) {
                float4 q4 = *reinterpret_cast<float4*>(&sQ[r][k]);
                float4 k40 = *reinterpret_cast<float4*>(&sKV[j0 + 0][k]);
                float4 k41 = *reinterpret_cast<float4*>(&sKV[j0 + 1][k]);
                float4 k42 = *reinterpret_cast<float4*>(&sKV[j0 + 2][k]);
                float4 k43 = *reinterpret_cast<float4*>(&sKV[j0 + 3][k]);
                s0 += q4.x * k40.x + q4.y * k40.y + q4.z * k40.z + q4.w * k40.w;
                s1 += q4.x * k41.x + q4.y * k41.y + q4.z * k41.z + q4.w * k41.w;
                s2 += q4.x * k42.x + q4.y * k42.y + q4.z * k42.z + q4.w * k42.w;
                s3 += q4.x * k43.x + q4.y * k43.y + q4.z * k43.z + q4.w * k43.w;
            }
            int kg = kt * 32 + j0;
            sS[r][j0 + 0] = (kg + 0 > qrow_g) ? -1e30f : s0;
            sS[r][j0 + 1] = (kg + 1 > qrow_g) ? -1e30f : s1;
            sS[r][j0 + 2] = (kg + 2 > qrow_g) ? -1e30f : s2;
            sS[r][j0 + 3] = (kg + 3 > qrow_g) ? -1e30f : s3;
        }
        __syncthreads();

        if (t < 32) {
            float mx = -1e30f;
#pragma unroll
            for (int j = 0; j < 32; j++) mx = fmaxf(mx, sS[t][j]);
            float mn = fmaxf(sM[t], mx);
            float al = exp2f(fminf(sM[t] - mn, 0.f));
            float ls = 0.f;
#pragma unroll
            for (int j = 0; j < 32; j++) {
                float p = exp2f(fminf(sS[t][j] - mn, 0.f));
                sS[t][j] = p;
                ls += p;
            }
            sL[t] = sL[t] * al + ls;
            sM[t] = mn;
            sAl[t] = al;
        }
        __syncthreads();

        float al = sAl[r];
#pragma unroll
        for (int i = 0; i < 16; i++) o[i] *= al;

        const float* vb = vb0 + (size_t)kt * 32 * HD_;
#pragma unroll
        for (int i = 0; i < 16; i++) {
            int idx = t + i * 256;
            sKV[idx >> 7][idx & 127] = vb[idx];
        }
        __syncthreads();

#pragma unroll 4
        for (int j = 0; j < 32; j++) {
            float p = sS[r][j];
            float4 v0 = *reinterpret_cast<float4*>(&sKV[j][dbase]);
            float4 v1 = *reinterpret_cast<float4*>(&sKV[j][dbase + 4]);
            float4 v2 = *reinterpret_cast<float4*>(&sKV[j][dbase + 8]);
            float4 v3 = *reinterpret_cast<float4*>(&sKV[j][dbase + 12]);
            o[0]  += p * v0.x; o[1]  += p * v0.y; o[2]  += p * v0.z; o[3]  += p * v0.w;
            o[4]  += p * v1.x; o[5]  += p * v1.y; o[6]  += p * v1.z; o[7]  += p * v1.w;
            o[8]  += p * v2.x; o[9]  += p * v2.y; o[10] += p * v2.z; o[11] += p * v2.w;
            o[12] += p * v3.x; o[13] += p * v3.y; o[14] += p * v3.z; o[15] += p * v3.w;
        }
        __syncthreads();
    }

    float inv = 1.f / fmaxf(sL[r], 1e-20f);
    size_t obase = (size_t)(b * S_ + qt * 32 + r) * H_ + h * 128 + dbase;
#pragma unroll
    for (int i = 0; i < 16; i++) gf_ctx[obase + i] = san(o[i] * inv, 4);
}

// ---- canary: exponent-coded first failing stage into out[0] ----
__global__ void canary_kernel(float* __restrict__ outp) {
    if (threadIdx.x == 0 && blockIdx.x == 0) {
        if (g_flags[6]) { outp[0] += 3.0e38f; return; }
        const float code[6] = {1e6f, 1e12f, 1e18f, 1e24f, 1e30f, 1e36f};
        for (int i = 0; i < 6; i++) {
            if (g_flags[i]) { outp[0] += code[i]; return; }
        }
    }
}

extern "C" void kernel_launch(void* const* d_in, const int* in_sizes, int n_in,
                              void* d_out, int out_size) {
    int iw[4], nw = 0;
    long long ws = -1;
    for (int i = 0; i < n_in; i++) {
        int cnt = 0;
        for (int j = 0; j < n_in; j++) if (in_sizes[j] == in_sizes[i]) cnt++;
        if (cnt == 4) ws = in_sizes[i];
    }
    int ix = 0, inw = 1, ipos = 6;
    if (ws > 0) {
        int rem[8], nrem = 0;
        for (int i = 0; i < n_in; i++) {
            if (in_sizes[i] == (int)ws && nw < 4) iw[nw++] = i;
            else if ((long long)in_sizes[i] == 2 * ws) ix = i;
            else if (nrem < 8) rem[nrem++] = i;
        }
        if (nrem >= 2) {
            if (in_sizes[rem[0]] <= in_sizes[rem[1]]) { inw = rem[0]; ipos = rem[1]; }
            else                                      { inw = rem[1]; ipos = rem[0]; }
        }
    }
    if (nw < 4) { iw[0] = 2; iw[1] = 3; iw[2] = 4; iw[3] = 5; ix = 0; inw = 1; ipos = 6; }

    const float* x      = (const float*)d_in[ix];
    const float* norm_w = (const float*)d_in[inw];
    const int*   pos    = (const int*)d_in[ipos];
    float* outp = (float*)d_out;

    zero_flags_kernel<<<1, 32>>>();
    probe_kernel<<<1, 256>>>(x);

    rmsnorm_kernel<<<M_, 256>>>(x, norm_w);

    dim3 gg(H_ / 128, M_ / 128);
    gemm_kernel<0><<<gg, 256>>>((const float*)d_in[iw[0]], nullptr);
    gemm_kernel<1><<<gg, 256>>>((const float*)d_in[iw[1]], nullptr);
    gemm_kernel<2><<<gg, 256>>>((const float*)d_in[iw[2]], nullptr);

    rope_kernel<<<(B_ * NH_ * S_) / 2, 128>>>(pos);

    dim3 fg(S_ / 32, B_ * NH_);
    fa_kernel<<<fg, 256>>>();

    gemm_kernel<3><<<gg, 256>>>((const float*)d_in[iw[3]], outp);
    canary_kernel<<<1, 32>>>(outp);
}